// round 17
// baseline (speedup 1.0000x reference)
#include <cuda_runtime.h>
#include <cuda_fp16.h>
#include <cstdint>

namespace {

constexpr int Bv = 2, Hv = 16, Sv = 2048, Dv = 64;
constexpr int BM = 128;   // query rows per CTA (32 per warp)
constexpr int BN = 64;    // kv rows per tile (doubled: amortize softmax/barrier overhead)
constexpr int NT = Sv / BN;
constexpr int KS2 = 36;   // sK2 half2 stride: frag banks (4g+t), conflict-free
constexpr int VS2 = 72;   // sV2 half2 stride: frag banks (8t+g), conflict-free
constexpr float QSCALE = 0.125f * 1.44269504089f;  // 1/sqrt(64) * log2(e)

// Packed mask bits: pm[b][col_group][row], col_group = 32 cols. 1 MB scratch.
__device__ uint32_t d_pm[(size_t)Bv * (Sv / 32) * Sv];

// 8 lanes per packed word; each lane loads int4 (4 cols) and contributes a nibble.
__global__ void __launch_bounds__(256)
pack_mask_kernel(const int* __restrict__ mask) {
    int gtid = blockIdx.x * 256 + threadIdx.x;
    int w   = gtid >> 3;                 // word index = (b*64 + cg)*2048 + row
    int sub = gtid & 7;
    int row = w & (Sv - 1);
    int cg  = (w >> 11) & (Sv / 32 - 1);
    int b   = w >> 17;
    int4 v = *reinterpret_cast<const int4*>(
        mask + ((size_t)b * Sv + row) * Sv + cg * 32 + sub * 4);
    uint32_t nib = (v.x != 0 ? 1u : 0u) | (v.y != 0 ? 2u : 0u) |
                   (v.z != 0 ? 4u : 0u) | (v.w != 0 ? 8u : 0u);
    uint32_t val = nib << (4 * sub);
    val |= __shfl_xor_sync(0xffffffffu, val, 1);
    val |= __shfl_xor_sync(0xffffffffu, val, 2);
    val |= __shfl_xor_sync(0xffffffffu, val, 4);
    if (sub == 0) d_pm[w] = val;
}

__device__ __forceinline__ uint32_t h2(float lo, float hi) {
    __half2 h = __floats2half2_rn(lo, hi);
    return *reinterpret_cast<uint32_t*>(&h);
}

__device__ __forceinline__ void mma16(float* c, const uint32_t* a, const uint32_t* b) {
    asm volatile(
        "mma.sync.aligned.m16n8k16.row.col.f32.f16.f16.f32 "
        "{%0,%1,%2,%3}, {%4,%5,%6,%7}, {%8,%9}, {%0,%1,%2,%3};"
        : "+f"(c[0]), "+f"(c[1]), "+f"(c[2]), "+f"(c[3])
        : "r"(a[0]), "r"(a[1]), "r"(a[2]), "r"(a[3]), "r"(b[0]), "r"(b[1]));
}

__global__ void __launch_bounds__(128, 2)
attn_kernel(const float* __restrict__ q, const float* __restrict__ k,
            const float* __restrict__ v, float* __restrict__ out) {
    __shared__ uint32_t sK2[2][BN * KS2];        // 64 rows x (32 half2 + pad)
    __shared__ uint32_t sV2[2][(BN / 2) * VS2];  // 32 kv-pairs x (64 d + pad)

    const int tid = threadIdx.x;
    const int warp = tid >> 5;
    const int lane = tid & 31;
    const int g = lane >> 2;
    const int t = lane & 3;
    const int base = warp * 32;
    const int rA0 = base + g;
    const int rA1 = base + 16 + g;

    const int bh = blockIdx.y;
    const int b  = bh >> 4;          // H = 16
    const int q0 = blockIdx.x * BM;

    const float* qg = q + ((size_t)bh * Sv + q0) * Dv;
    const float* kg = k + (size_t)bh * Sv * Dv;
    const float* vg = v + (size_t)bh * Sv * Dv;
    float*       og = out + ((size_t)bh * Sv + q0) * Dv;

    // packed-mask pointer: lane <-> row (base+lane); 2 words (lo/hi 32 cols) per tile
    const uint32_t* pmp = d_pm + ((size_t)b * (Sv / 32)) * Sv + q0 + base + lane;

    // ---- Q A-fragments for both row-frags: scaled + converted ONCE (32 regs) ----
    uint32_t qh[2][4][4];
#pragma unroll
    for (int f = 0; f < 2; f++) {
        const int rA = base + f * 16 + g, rB = rA + 8;
#pragma unroll
        for (int kc = 0; kc < 4; kc++) {
            const int kk = kc * 16 + 2 * t;
            float2 x0 = *reinterpret_cast<const float2*>(qg + (size_t)rA * Dv + kk);
            float2 x1 = *reinterpret_cast<const float2*>(qg + (size_t)rB * Dv + kk);
            float2 x2 = *reinterpret_cast<const float2*>(qg + (size_t)rA * Dv + kk + 8);
            float2 x3 = *reinterpret_cast<const float2*>(qg + (size_t)rB * Dv + kk + 8);
            qh[f][kc][0] = h2(x0.x * QSCALE, x0.y * QSCALE);
            qh[f][kc][1] = h2(x1.x * QSCALE, x1.y * QSCALE);
            qh[f][kc][2] = h2(x2.x * QSCALE, x2.y * QSCALE);
            qh[f][kc][3] = h2(x3.x * QSCALE, x3.y * QSCALE);
        }
    }

    // Stage mappings: K rows (kro, kro+32), V pair-rows (vk2, vk2+16)
    const int kro = tid >> 2, kds = tid & 3;
    const int vk2 = tid >> 3, vsg = tid & 7;
    const float* kp  = kg + (size_t)kro * Dv + kds * 16;
    const float* vp0 = vg + (size_t)(2 * vk2) * Dv + vsg * 8;

    // ---- prefetch tile 0: LDG f32, convert to half2 in regs immediately ----
    uint32_t kha[8], khb[8], vha[8], vhb[8];
    uint32_t pmwL, pmwH;
    {
#pragma unroll
        for (int h = 0; h < 2; h++) {
            const float* kq = kp + (size_t)h * 32 * Dv;
            float4 a = *reinterpret_cast<const float4*>(kq);
            float4 bb = *reinterpret_cast<const float4*>(kq + 4);
            float4 c = *reinterpret_cast<const float4*>(kq + 8);
            float4 d = *reinterpret_cast<const float4*>(kq + 12);
            uint32_t* kh = h ? khb : kha;
            kh[0] = h2(a.x, a.y); kh[1] = h2(a.z, a.w);
            kh[2] = h2(bb.x, bb.y); kh[3] = h2(bb.z, bb.w);
            kh[4] = h2(c.x, c.y); kh[5] = h2(c.z, c.w);
            kh[6] = h2(d.x, d.y); kh[7] = h2(d.z, d.w);
            const float* v0 = vp0 + (size_t)h * 32 * Dv;
            const float* v1 = v0 + Dv;
            float4 a0 = *reinterpret_cast<const float4*>(v0);
            float4 a1 = *reinterpret_cast<const float4*>(v0 + 4);
            float4 b0 = *reinterpret_cast<const float4*>(v1);
            float4 b1 = *reinterpret_cast<const float4*>(v1 + 4);
            uint32_t* vh = h ? vhb : vha;
            vh[0] = h2(a0.x, b0.x); vh[1] = h2(a0.y, b0.y);
            vh[2] = h2(a0.z, b0.z); vh[3] = h2(a0.w, b0.w);
            vh[4] = h2(a1.x, b1.x); vh[5] = h2(a1.y, b1.y);
            vh[6] = h2(a1.z, b1.z); vh[7] = h2(a1.w, b1.w);
        }
        kp += BN * Dv; vp0 += BN * Dv;
        pmwL = pmp[0];
        pmwH = pmp[Sv];
        pmp += 2 * Sv;
    }

    float o0[8][4], o1[8][4];
#pragma unroll
    for (int i = 0; i < 8; i++)
#pragma unroll
        for (int j = 0; j < 4; j++) { o0[i][j] = 0.f; o1[i][j] = 0.f; }
    float m0 = -1e30f, m1 = -1e30f, m2 = -1e30f, m3 = -1e30f;
    // l* are PER-THREAD PARTIAL sums; reduced across the quad in the epilogue.
    float l0 = 0.f, l1 = 0.f, l2 = 0.f, l3 = 0.f;

    for (int kt = 0; kt < NT; kt++) {
        const int cur = kt & 1;

        // ---- store prefetched half2 regs -> smem[cur] ----
        {
            uint32_t* dK = &sK2[cur][kro * KS2 + kds * 8];
            *reinterpret_cast<uint4*>(dK) = make_uint4(kha[0], kha[1], kha[2], kha[3]);
            *reinterpret_cast<uint4*>(dK + 4) = make_uint4(kha[4], kha[5], kha[6], kha[7]);
            uint32_t* dK2 = dK + 32 * KS2;
            *reinterpret_cast<uint4*>(dK2) = make_uint4(khb[0], khb[1], khb[2], khb[3]);
            *reinterpret_cast<uint4*>(dK2 + 4) = make_uint4(khb[4], khb[5], khb[6], khb[7]);
            uint32_t* dV = &sV2[cur][vk2 * VS2 + vsg * 8];
            *reinterpret_cast<uint4*>(dV) = make_uint4(vha[0], vha[1], vha[2], vha[3]);
            *reinterpret_cast<uint4*>(dV + 4) = make_uint4(vha[4], vha[5], vha[6], vha[7]);
            uint32_t* dV2 = dV + 16 * VS2;
            *reinterpret_cast<uint4*>(dV2) = make_uint4(vhb[0], vhb[1], vhb[2], vhb[3]);
            *reinterpret_cast<uint4*>(dV2 + 4) = make_uint4(vhb[4], vhb[5], vhb[6], vhb[7]);
        }
        __syncthreads();  // single barrier per 64-col tile

        const uint32_t pmLc = pmwL, pmHc = pmwH;

        // ---- prefetch NEXT tile (LDG + convert hidden under compute) ----
        if (kt + 1 < NT) {
#pragma unroll
            for (int h = 0; h < 2; h++) {
                const float* kq = kp + (size_t)h * 32 * Dv;
                float4 a = *reinterpret_cast<const float4*>(kq);
                float4 bb = *reinterpret_cast<const float4*>(kq + 4);
                float4 c = *reinterpret_cast<const float4*>(kq + 8);
                float4 d = *reinterpret_cast<const float4*>(kq + 12);
                uint32_t* kh = h ? khb : kha;
                kh[0] = h2(a.x, a.y); kh[1] = h2(a.z, a.w);
                kh[2] = h2(bb.x, bb.y); kh[3] = h2(bb.z, bb.w);
                kh[4] = h2(c.x, c.y); kh[5] = h2(c.z, c.w);
                kh[6] = h2(d.x, d.y); kh[7] = h2(d.z, d.w);
                const float* v0 = vp0 + (size_t)h * 32 * Dv;
                const float* v1 = v0 + Dv;
                float4 a0 = *reinterpret_cast<const float4*>(v0);
                float4 a1 = *reinterpret_cast<const float4*>(v0 + 4);
                float4 b0 = *reinterpret_cast<const float4*>(v1);
                float4 b1 = *reinterpret_cast<const float4*>(v1 + 4);
                uint32_t* vh = h ? vhb : vha;
                vh[0] = h2(a0.x, b0.x); vh[1] = h2(a0.y, b0.y);
                vh[2] = h2(a0.z, b0.z); vh[3] = h2(a0.w, b0.w);
                vh[4] = h2(a1.x, b1.x); vh[5] = h2(a1.y, b1.y);
                vh[6] = h2(a1.z, b1.z); vh[7] = h2(a1.w, b1.w);
            }
            kp += BN * Dv; vp0 += BN * Dv;
            pmwL = pmp[0];
            pmwH = pmp[Sv];
            pmp += 2 * Sv;
        }

        // ---- redistribute mask words to fragment rows ----
        const uint32_t wA0L = __shfl_sync(0xffffffffu, pmLc, g);
        const uint32_t wA0H = __shfl_sync(0xffffffffu, pmHc, g);
        const uint32_t wB0L = __shfl_sync(0xffffffffu, pmLc, g + 8);
        const uint32_t wB0H = __shfl_sync(0xffffffffu, pmHc, g + 8);
        const uint32_t wA1L = __shfl_sync(0xffffffffu, pmLc, g + 16);
        const uint32_t wA1H = __shfl_sync(0xffffffffu, pmHc, g + 16);
        const uint32_t wB1L = __shfl_sync(0xffffffffu, pmLc, g + 24);
        const uint32_t wB1H = __shfl_sync(0xffffffffu, pmHc, g + 24);
        const int sh = 2 * t;

        // ---- S = Q @ K^T over 64 cols: each b-frag load feeds BOTH row-frags ----
        float s0[8][4], s1[8][4];
#pragma unroll
        for (int nc = 0; nc < 8; nc++)
#pragma unroll
            for (int j = 0; j < 4; j++) { s0[nc][j] = 0.f; s1[nc][j] = 0.f; }

#pragma unroll
        for (int kc = 0; kc < 4; kc++) {
#pragma unroll
            for (int nc = 0; nc < 8; nc++) {
                uint32_t bv[2] = {sK2[cur][(nc * 8 + g) * KS2 + kc * 8 + t],
                                  sK2[cur][(nc * 8 + g) * KS2 + kc * 8 + t + 4]};
                mma16(s0[nc], qh[0][kc], bv);
                mma16(s1[nc], qh[1][kc], bv);
            }
        }

        // ---- softmax frag0 over 64 cols -> register-resident P ----
        uint32_t pa0[8][2];
        {
            float mx0 = -1e30f, mx1 = -1e30f;
#pragma unroll
            for (int nc = 0; nc < 8; nc++) {
                const uint32_t wA = (nc < 4) ? wA0L : wA0H;
                const uint32_t wB = (nc < 4) ? wB0L : wB0H;
                const int c = (nc & 3) * 8 + sh;
                s0[nc][0] = ((wA >> c) & 1u) ? s0[nc][0] : -1e9f;
                s0[nc][1] = ((wA >> (c + 1)) & 1u) ? s0[nc][1] : -1e9f;
                s0[nc][2] = ((wB >> c) & 1u) ? s0[nc][2] : -1e9f;
                s0[nc][3] = ((wB >> (c + 1)) & 1u) ? s0[nc][3] : -1e9f;
                mx0 = fmaxf(mx0, fmaxf(s0[nc][0], s0[nc][1]));
                mx1 = fmaxf(mx1, fmaxf(s0[nc][2], s0[nc][3]));
            }
            mx0 = fmaxf(mx0, __shfl_xor_sync(0xffffffffu, mx0, 1));
            mx0 = fmaxf(mx0, __shfl_xor_sync(0xffffffffu, mx0, 2));
            mx1 = fmaxf(mx1, __shfl_xor_sync(0xffffffffu, mx1, 1));
            mx1 = fmaxf(mx1, __shfl_xor_sync(0xffffffffu, mx1, 2));
            float mn0 = fmaxf(m0, mx0), mn1 = fmaxf(m1, mx1);
            float a0 = exp2f(m0 - mn0), a1 = exp2f(m1 - mn1);
            m0 = mn0; m1 = mn1;
            float rs0 = 0.f, rs1 = 0.f;
#pragma unroll
            for (int nc = 0; nc < 8; nc++) {
                float p00 = exp2f(s0[nc][0] - mn0);
                float p01 = exp2f(s0[nc][1] - mn0);
                float p10 = exp2f(s0[nc][2] - mn1);
                float p11 = exp2f(s0[nc][3] - mn1);
                rs0 += p00 + p01; rs1 += p10 + p11;
                pa0[nc][0] = h2(p00, p01);
                pa0[nc][1] = h2(p10, p11);
            }
            l0 = l0 * a0 + rs0;
            l1 = l1 * a1 + rs1;
            if (__any_sync(0xffffffffu, (a0 < 1.f) | (a1 < 1.f))) {
#pragma unroll
                for (int nc = 0; nc < 8; nc++) {
                    o0[nc][0] *= a0; o0[nc][1] *= a0;
                    o0[nc][2] *= a1; o0[nc][3] *= a1;
                }
            }
        }

        // ---- softmax frag1 ----
        uint32_t pa1[8][2];
        {
            float mx0 = -1e30f, mx1 = -1e30f;
#pragma unroll
            for (int nc = 0; nc < 8; nc++) {
                const uint32_t wA = (nc < 4) ? wA1L : wA1H;
                const uint32_t wB = (nc < 4) ? wB1L : wB1H;
                const int c = (nc & 3) * 8 + sh;
                s1[nc][0] = ((wA >> c) & 1u) ? s1[nc][0] : -1e9f;
                s1[nc][1] = ((wA >> (c + 1)) & 1u) ? s1[nc][1] : -1e9f;
                s1[nc][2] = ((wB >> c) & 1u) ? s1[nc][2] : -1e9f;
                s1[nc][3] = ((wB >> (c + 1)) & 1u) ? s1[nc][3] : -1e9f;
                mx0 = fmaxf(mx0, fmaxf(s1[nc][0], s1[nc][1]));
                mx1 = fmaxf(mx1, fmaxf(s1[nc][2], s1[nc][3]));
            }
            mx0 = fmaxf(mx0, __shfl_xor_sync(0xffffffffu, mx0, 1));
            mx0 = fmaxf(mx0, __shfl_xor_sync(0xffffffffu, mx0, 2));
            mx1 = fmaxf(mx1, __shfl_xor_sync(0xffffffffu, mx1, 1));
            mx1 = fmaxf(mx1, __shfl_xor_sync(0xffffffffu, mx1, 2));
            float mn0 = fmaxf(m2, mx0), mn1 = fmaxf(m3, mx1);
            float a0 = exp2f(m2 - mn0), a1 = exp2f(m3 - mn1);
            m2 = mn0; m3 = mn1;
            float rs0 = 0.f, rs1 = 0.f;
#pragma unroll
            for (int nc = 0; nc < 8; nc++) {
                float p00 = exp2f(s1[nc][0] - mn0);
                float p01 = exp2f(s1[nc][1] - mn0);
                float p10 = exp2f(s1[nc][2] - mn1);
                float p11 = exp2f(s1[nc][3] - mn1);
                rs0 += p00 + p01; rs1 += p10 + p11;
                pa1[nc][0] = h2(p00, p01);
                pa1[nc][1] = h2(p10, p11);
            }
            l2 = l2 * a0 + rs0;
            l3 = l3 * a1 + rs1;
            if (__any_sync(0xffffffffu, (a0 < 1.f) | (a1 < 1.f))) {
#pragma unroll
                for (int nc = 0; nc < 8; nc++) {
                    o1[nc][0] *= a0; o1[nc][1] *= a0;
                    o1[nc][2] *= a1; o1[nc][3] *= a1;
                }
            }
        }

        // ---- O += P @ V over 64 kv: each pb load feeds BOTH row-frags ----
#pragma unroll
        for (int kc2 = 0; kc2 < 4; kc2++) {
            uint32_t a0v[4] = {pa0[2 * kc2][0], pa0[2 * kc2][1],
                               pa0[2 * kc2 + 1][0], pa0[2 * kc2 + 1][1]};
            uint32_t a1v[4] = {pa1[2 * kc2][0], pa1[2 * kc2][1],
                               pa1[2 * kc2 + 1][0], pa1[2 * kc2 + 1][1]};
#pragma unroll
            for (int nc = 0; nc < 8; nc++) {
                uint32_t pb[2] = {sV2[cur][(kc2 * 8 + t) * VS2 + nc * 8 + g],
                                  sV2[cur][(kc2 * 8 + t + 4) * VS2 + nc * 8 + g]};
                mma16(o0[nc], a0v, pb);
                mma16(o1[nc], a1v, pb);
            }
        }
    }

    // ---- epilogue: reduce l partials across the quad, then scale + store ----
    {
        l0 += __shfl_xor_sync(0xffffffffu, l0, 1);
        l0 += __shfl_xor_sync(0xffffffffu, l0, 2);
        l1 += __shfl_xor_sync(0xffffffffu, l1, 1);
        l1 += __shfl_xor_sync(0xffffffffu, l1, 2);
        l2 += __shfl_xor_sync(0xffffffffu, l2, 1);
        l2 += __shfl_xor_sync(0xffffffffu, l2, 2);
        l3 += __shfl_xor_sync(0xffffffffu, l3, 1);
        l3 += __shfl_xor_sync(0xffffffffu, l3, 2);
        float i0 = 1.f / l0, i1 = 1.f / l1, i2 = 1.f / l2, i3 = 1.f / l3;
#pragma unroll
        for (int nc = 0; nc < 8; nc++) {
            int c0 = nc * 8 + 2 * t;
            *reinterpret_cast<float2*>(og + (size_t)rA0 * Dv + c0) =
                make_float2(o0[nc][0] * i0, o0[nc][1] * i0);
            *reinterpret_cast<float2*>(og + (size_t)(rA0 + 8) * Dv + c0) =
                make_float2(o0[nc][2] * i1, o0[nc][3] * i1);
            *reinterpret_cast<float2*>(og + (size_t)rA1 * Dv + c0) =
                make_float2(o1[nc][0] * i2, o1[nc][1] * i2);
            *reinterpret_cast<float2*>(og + (size_t)(rA1 + 8) * Dv + c0) =
                make_float2(o1[nc][2] * i3, o1[nc][3] * i3);
        }
    }
}

}  // namespace

extern "C" void kernel_launch(void* const* d_in, const int* in_sizes, int n_in,
                              void* d_out, int out_size) {
    const float* q = (const float*)d_in[0];
    const float* k = (const float*)d_in[1];
    const float* v = (const float*)d_in[2];
    const int* mask = (const int*)d_in[3];
    float* out = (float*)d_out;

    // Pre-pass: pack mask int32 -> bits (tile-major layout), int4 + nibble OR
    int total_threads = Bv * (Sv / 32) * Sv * 8;  // 8 lanes per packed word
    pack_mask_kernel<<<total_threads / 256, 256>>>(mask);

    dim3 grid(Sv / BM, Bv * Hv);  // (16, 32)
    dim3 block(128);
    attn_kernel<<<grid, block>>>(q, k, v, out);
}